// round 9
// baseline (speedup 1.0000x reference)
#include <cuda_runtime.h>
#include <cuda_bf16.h>
#include <cstdint>
#include <math.h>

// NT-Xent loss, N=4096, D=256.
// loss = mean_i( log(sum_{j!=i} e^{2 zn_i.zn_j}) - 2 zn_i.zn_{i^4096} )
// R9: single persistent kernel (148 CTAs, 1/SM): normalize -> grid sync ->
//     symmetric HMMA GEMM (R6 core) -> grid sync -> CTA0 finish.

#define NROWS 8192
#define NHALF 4096
#define DDIM  256
#define BM 128
#define NTILE 64
#define NCTA 148
#define TILE_BYTES (BM * DDIM * 2)        // 65536
#define RED_BYTES ((4 + 2) * BM * 4)

__device__ __align__(16) __nv_bfloat16 g_zb[NROWS * DDIM];
__device__ float g_rowsum[NROWS];
__device__ float g_pair[NROWS];
__device__ unsigned g_cnt1;
__device__ unsigned g_cnt2;

// ---------------------------------------------------------------- helpers
__device__ __forceinline__ uint32_t smem_u32(const void* p) {
    uint32_t a;
    asm("{ .reg .u64 t; cvta.to.shared.u64 t, %1; cvt.u32.u64 %0, t; }" : "=r"(a) : "l"(p));
    return a;
}
__device__ __forceinline__ void ldsm_x4(uint32_t addr, uint32_t* r) {
    asm volatile("ldmatrix.sync.aligned.m8n8.x4.shared.b16 {%0,%1,%2,%3}, [%4];"
        : "=r"(r[0]), "=r"(r[1]), "=r"(r[2]), "=r"(r[3]) : "r"(addr));
}
__device__ __forceinline__ void mma16816(float* c, const uint32_t* a, const uint32_t* b) {
    asm volatile("mma.sync.aligned.m16n8k16.row.col.f32.bf16.bf16.f32 "
        "{%0,%1,%2,%3}, {%4,%5,%6,%7}, {%8,%9}, {%0,%1,%2,%3};"
        : "+f"(c[0]), "+f"(c[1]), "+f"(c[2]), "+f"(c[3])
        : "r"(a[0]), "r"(a[1]), "r"(a[2]), "r"(a[3]), "r"(b[0]), "r"(b[1]));
}
__device__ __forceinline__ void cp_async16(uint32_t dst, const void* src) {
    asm volatile("cp.async.cg.shared.global [%0], [%1], 16;" :: "r"(dst), "l"(src));
}
#define CP_COMMIT() asm volatile("cp.async.commit_group;" ::: "memory")
#define CP_WAIT0()  asm volatile("cp.async.wait_group 0;" ::: "memory")

__device__ __forceinline__ uint32_t tile_addr(uint32_t base, int row, int chunk) {
    return base + (uint32_t)row * 512u + (uint32_t)((chunk ^ (row & 7)) << 4);
}
__device__ __forceinline__ int rowof(int p) {
    return (p & 1) ? (NTILE - 1 - (p >> 1)) : (p >> 1);
}
__device__ __forceinline__ void tile_load(uint32_t ubase, int row0, int tid) {
    #pragma unroll
    for (int it = 0; it < 16; it++) {
        int idx = tid + it * 256;
        int r = idx >> 5, c = idx & 31;
        cp_async16(tile_addr(ubase, r, c), g_zb + (size_t)(row0 + r) * DDIM + c * 8);
    }
}

// ---------------------------------------------------------- fused persistent kernel
__global__ __launch_bounds__(256, 1) void k_fused(const float* __restrict__ z1,
                                                  const float* __restrict__ z2,
                                                  float* __restrict__ out) {
    extern __shared__ __align__(16) char dyn[];
    const int tid = threadIdx.x;
    const int wid = tid >> 5;
    const int lane = tid & 31;
    const int wm = wid & 1;
    const int wn = wid >> 1;
    const int cta = blockIdx.x;

    // ---------------- phase 1: normalize (warp per row, striped over CTAs) ----------
    #pragma unroll
    for (int it = 0; it < 7; it++) {
        const int grp = cta + it * NCTA;          // 8-row group
        if (grp < NROWS / 8) {
            const int row = grp * 8 + wid;
            const float* src = (row < NHALF) ? (z1 + (size_t)row * DDIM)
                                             : (z2 + (size_t)(row - NHALF) * DDIM);
            float4 v0 = ((const float4*)src)[lane];
            float4 v1 = ((const float4*)src)[lane + 32];
            float ss = v0.x * v0.x + v0.y * v0.y + v0.z * v0.z + v0.w * v0.w
                     + v1.x * v1.x + v1.y * v1.y + v1.z * v1.z + v1.w * v1.w;
            #pragma unroll
            for (int o = 16; o; o >>= 1) ss += __shfl_xor_sync(0xFFFFFFFFu, ss, o);
            const float rn = 1.0f / fmaxf(sqrtf(ss), 1e-8f);
            __nv_bfloat16* dst = g_zb + (size_t)row * DDIM;
            __nv_bfloat162 b0 = {__float2bfloat16(v0.x * rn), __float2bfloat16(v0.y * rn)};
            __nv_bfloat162 b1 = {__float2bfloat16(v0.z * rn), __float2bfloat16(v0.w * rn)};
            __nv_bfloat162 b2 = {__float2bfloat16(v1.x * rn), __float2bfloat16(v1.y * rn)};
            __nv_bfloat162 b3 = {__float2bfloat16(v1.z * rn), __float2bfloat16(v1.w * rn)};
            ((__nv_bfloat162*)dst)[lane * 2]            = b0;
            ((__nv_bfloat162*)dst)[lane * 2 + 1]        = b1;
            ((__nv_bfloat162*)dst)[(lane + 32) * 2]     = b2;
            ((__nv_bfloat162*)dst)[(lane + 32) * 2 + 1] = b3;
            if (lane == 0) g_rowsum[row] = 0.0f;
        }
    }

    // ---------------- grid barrier 1 (all 148 CTAs are co-resident) ----------------
    if (tid == 0) {
        __threadfence();
        atomicAdd(&g_cnt1, 1u);
        while (*(volatile unsigned*)&g_cnt1 < NCTA) { }
        __threadfence();
    }
    __syncthreads();

    // ---------------- phase 2: symmetric HMMA GEMM + exp + sums + pair -------------
    uint32_t d32 = smem_u32(dyn);
    char* base = dyn + ((1024u - (d32 & 1023u)) & 1023u);
    const uint32_t uA  = smem_u32(base);
    const uint32_t uB0 = uA + TILE_BYTES;
    const uint32_t uB1 = uA + 2 * TILE_BYTES;
    float* red_row = (float*)(base + 3 * TILE_BYTES);
    float* red_col = red_row + 4 * BM;

    const int count = 14 + (cta < 8 ? 1 : 0);
    int rem = cta * 14 + (cta < 8 ? cta : 8);
    int p = 0;
    for (;;) {
        int L = NTILE - rowof(p);
        if (rem < L) break;
        rem -= L;
        p++;
    }
    int off = rem;

    int ti = rowof(p);
    tile_load(uA, ti * BM, tid);
    tile_load(uB0, (ti + off) * BM, tid);
    CP_COMMIT();
    int cur_ti = ti;

    for (int k = 0; k < count; k++) {
        ti = rowof(p);
        const int tj = ti + off;
        if (ti != cur_ti) {
            tile_load(uA, ti * BM, tid);
            CP_COMMIT();
            cur_ti = ti;
        }
        CP_WAIT0();
        __syncthreads();

        if (k + 1 < count) {
            int p2 = p, o2 = off + 1;
            if (o2 >= NTILE - rowof(p2)) { o2 = 0; p2++; }
            tile_load((k & 1) ? uB0 : uB1, (rowof(p2) + o2) * BM, tid);
            CP_COMMIT();
        }

        const uint32_t uBc = (k & 1) ? uB1 : uB0;
        const int i0 = ti * BM, j0 = tj * BM;
        const bool diag = (ti == tj);
        const bool pairt = (tj == ti + NHALF / BM);

        float acc[4][4][4];
        #pragma unroll
        for (int mf = 0; mf < 4; mf++)
            #pragma unroll
            for (int nf = 0; nf < 4; nf++)
                #pragma unroll
                for (int c = 0; c < 4; c++) acc[mf][nf][c] = 0.0f;

        #pragma unroll 4
        for (int ks = 0; ks < 16; ks++) {
            const int cch = ks * 2 + (lane >> 4);
            uint32_t af[4][4], bf[4][2];
            #pragma unroll
            for (int mf = 0; mf < 4; mf++) {
                int r = wm * 64 + mf * 16 + (lane & 15);
                ldsm_x4(tile_addr(uA, r, cch), af[mf]);
            }
            #pragma unroll
            for (int ng = 0; ng < 2; ng++) {
                int rn = wn * 32 + ng * 16 + (lane & 15);
                uint32_t q[4];
                ldsm_x4(tile_addr(uBc, rn, cch), q);
                bf[ng * 2 + 0][0] = q[0]; bf[ng * 2 + 0][1] = q[2];
                bf[ng * 2 + 1][0] = q[1]; bf[ng * 2 + 1][1] = q[3];
            }
            #pragma unroll
            for (int mf = 0; mf < 4; mf++)
                #pragma unroll
                for (int nf = 0; nf < 4; nf++)
                    mma16816(acc[mf][nf], af[mf], bf[nf]);
        }

        const int rloc = wm * 64 + (lane >> 2);
        const int cloc = wn * 32 + (lane & 3) * 2;
        float cs[8];
        #pragma unroll
        for (int x = 0; x < 8; x++) cs[x] = 0.0f;

        #pragma unroll
        for (int mf = 0; mf < 4; mf++) {
            const int rlo = i0 + rloc + mf * 16;
            const int rhi = rlo + 8;
            float slo = 0.0f, shi = 0.0f;
            #pragma unroll
            for (int nf = 0; nf < 4; nf++) {
                const int col = j0 + cloc + nf * 8;
                if (pairt) {
                    if ((rlo ^ NHALF) == col) {
                        float v = 2.0f * acc[mf][nf][0];
                        g_pair[rlo] = v; g_pair[col] = v;
                    }
                    if ((rlo ^ NHALF) == col + 1) {
                        float v = 2.0f * acc[mf][nf][1];
                        g_pair[rlo] = v; g_pair[col + 1] = v;
                    }
                    if ((rhi ^ NHALF) == col) {
                        float v = 2.0f * acc[mf][nf][2];
                        g_pair[rhi] = v; g_pair[col] = v;
                    }
                    if ((rhi ^ NHALF) == col + 1) {
                        float v = 2.0f * acc[mf][nf][3];
                        g_pair[rhi] = v; g_pair[col + 1] = v;
                    }
                }
                float e0 = __expf(2.0f * acc[mf][nf][0]);
                float e1 = __expf(2.0f * acc[mf][nf][1]);
                float e2 = __expf(2.0f * acc[mf][nf][2]);
                float e3 = __expf(2.0f * acc[mf][nf][3]);
                e0 = (rlo == col)     ? 0.0f : e0;
                e1 = (rlo == col + 1) ? 0.0f : e1;
                e2 = (rhi == col)     ? 0.0f : e2;
                e3 = (rhi == col + 1) ? 0.0f : e3;
                slo += e0 + e1;
                shi += e2 + e3;
                cs[nf * 2]     += e0 + e2;
                cs[nf * 2 + 1] += e1 + e3;
            }
            slo += __shfl_xor_sync(0xFFFFFFFFu, slo, 1);
            slo += __shfl_xor_sync(0xFFFFFFFFu, slo, 2);
            shi += __shfl_xor_sync(0xFFFFFFFFu, shi, 1);
            shi += __shfl_xor_sync(0xFFFFFFFFu, shi, 2);
            if ((lane & 3) == 0) {
                const int lrow = wm * 64 + mf * 16 + (lane >> 2);
                red_row[wn * BM + lrow] = slo;
                red_row[wn * BM + lrow + 8] = shi;
            }
        }
        if (!diag) {
            #pragma unroll
            for (int x = 0; x < 8; x++) {
                cs[x] += __shfl_xor_sync(0xFFFFFFFFu, cs[x], 4);
                cs[x] += __shfl_xor_sync(0xFFFFFFFFu, cs[x], 8);
                cs[x] += __shfl_xor_sync(0xFFFFFFFFu, cs[x], 16);
            }
            if (lane < 4) {
                #pragma unroll
                for (int nf = 0; nf < 4; nf++) {
                    const int c = wn * 32 + nf * 8 + lane * 2;
                    red_col[wm * BM + c]     = cs[nf * 2];
                    red_col[wm * BM + c + 1] = cs[nf * 2 + 1];
                }
            }
        }
        __syncthreads();
        if (tid < BM) {
            float s = red_row[tid] + red_row[BM + tid]
                    + red_row[2 * BM + tid] + red_row[3 * BM + tid];
            atomicAdd(&g_rowsum[i0 + tid], s);
        } else if (!diag) {
            const int c = tid - BM;
            atomicAdd(&g_rowsum[j0 + c], red_col[c] + red_col[BM + c]);
        }

        off++;
        if (off >= NTILE - ti) { off = 0; p++; }
    }

    // ---------------- grid barrier 2 + CTA0 finish ---------------------------------
    if (tid == 0) {
        __threadfence();
        atomicAdd(&g_cnt2, 1u);
    }
    if (cta == 0) {
        if (tid == 0) {
            while (*(volatile unsigned*)&g_cnt2 < NCTA) { }
            __threadfence();
        }
        __syncthreads();
        __shared__ float sh[256];
        float s = 0.0f;
        #pragma unroll
        for (int u = 0; u < NROWS / 256; u++) {
            const int r = tid + u * 256;
            s += logf(g_rowsum[r]) - g_pair[r];
        }
        sh[tid] = s;
        __syncthreads();
        for (int o2 = 128; o2; o2 >>= 1) {
            if (tid < o2) sh[tid] += sh[tid + o2];
            __syncthreads();
        }
        if (tid == 0) {
            out[0] = sh[0] * (1.0f / (float)NROWS);
            g_cnt1 = 0;            // reset for next graph replay
            g_cnt2 = 0;
        }
    }
}

// ---------------------------------------------------------------- launch
extern "C" void kernel_launch(void* const* d_in, const int* in_sizes, int n_in,
                              void* d_out, int out_size) {
    const float* z1 = (const float*)d_in[0];
    const float* z2 = (const float*)d_in[1];
    float* out = (float*)d_out;

    static int smem_set = 0;
    if (!smem_set) {
        cudaFuncSetAttribute(k_fused, cudaFuncAttributeMaxDynamicSharedMemorySize,
                             3 * TILE_BYTES + RED_BYTES + 1024);
        smem_set = 1;
    }

    k_fused<<<NCTA, 256, 3 * TILE_BYTES + RED_BYTES + 1024>>>(z1, z2, out);
}

// round 11
// speedup vs baseline: 1.0319x; 1.0319x over previous
#include <cuda_runtime.h>
#include <cuda_bf16.h>
#include <cstdint>
#include <math.h>

// NT-Xent loss, N=4096, D=256.
// loss = mean_i( log(sum_{j!=i} e^{2 zn_i.zn_j}) - 2 zn_i.zn_{i^4096} )
// R10: persistent fused kernel, 512 threads/CTA (16 warps, 32x32 warp tiles)
//      to lift occupancy 12.4% -> 25% and feed the tensor pipe (was 37.7%).

#define NROWS 8192
#define NHALF 4096
#define DDIM  256
#define BM 128
#define NTILE 64
#define NCTA 148
#define NTHREADS 512
#define TILE_BYTES (BM * DDIM * 2)        // 65536
#define RED_BYTES (8 * BM * 4)            // red_row[4][128] + red_col[4][128]

__device__ __align__(16) __nv_bfloat16 g_zb[NROWS * DDIM];
__device__ float g_rowsum[NROWS];
__device__ float g_pair[NROWS];
__device__ unsigned g_cnt1;
__device__ unsigned g_cnt2;

// ---------------------------------------------------------------- helpers
__device__ __forceinline__ uint32_t smem_u32(const void* p) {
    uint32_t a;
    asm("{ .reg .u64 t; cvta.to.shared.u64 t, %1; cvt.u32.u64 %0, t; }" : "=r"(a) : "l"(p));
    return a;
}
__device__ __forceinline__ void ldsm_x4(uint32_t addr, uint32_t* r) {
    asm volatile("ldmatrix.sync.aligned.m8n8.x4.shared.b16 {%0,%1,%2,%3}, [%4];"
        : "=r"(r[0]), "=r"(r[1]), "=r"(r[2]), "=r"(r[3]) : "r"(addr));
}
__device__ __forceinline__ void mma16816(float* c, const uint32_t* a, const uint32_t* b) {
    asm volatile("mma.sync.aligned.m16n8k16.row.col.f32.bf16.bf16.f32 "
        "{%0,%1,%2,%3}, {%4,%5,%6,%7}, {%8,%9}, {%0,%1,%2,%3};"
        : "+f"(c[0]), "+f"(c[1]), "+f"(c[2]), "+f"(c[3])
        : "r"(a[0]), "r"(a[1]), "r"(a[2]), "r"(a[3]), "r"(b[0]), "r"(b[1]));
}
__device__ __forceinline__ void cp_async16(uint32_t dst, const void* src) {
    asm volatile("cp.async.cg.shared.global [%0], [%1], 16;" :: "r"(dst), "l"(src));
}
#define CP_COMMIT() asm volatile("cp.async.commit_group;" ::: "memory")
#define CP_WAIT0()  asm volatile("cp.async.wait_group 0;" ::: "memory")

__device__ __forceinline__ uint32_t tile_addr(uint32_t base, int row, int chunk) {
    return base + (uint32_t)row * 512u + (uint32_t)((chunk ^ (row & 7)) << 4);
}
__device__ __forceinline__ int rowof(int p) {
    return (p & 1) ? (NTILE - 1 - (p >> 1)) : (p >> 1);
}
__device__ __forceinline__ void tile_load(uint32_t ubase, int row0, int tid) {
    #pragma unroll
    for (int it = 0; it < 8; it++) {
        int idx = tid + it * NTHREADS;
        int r = idx >> 5, c = idx & 31;
        cp_async16(tile_addr(ubase, r, c), g_zb + (size_t)(row0 + r) * DDIM + c * 8);
    }
}

// ---------------------------------------------------------- fused persistent kernel
__global__ __launch_bounds__(NTHREADS, 1) void k_fused(const float* __restrict__ z1,
                                                       const float* __restrict__ z2,
                                                       float* __restrict__ out) {
    extern __shared__ __align__(16) char dyn[];
    const int tid = threadIdx.x;
    const int wid = tid >> 5;
    const int lane = tid & 31;
    const int wm = wid & 3;           // 4 row groups of 32
    const int wn = wid >> 2;          // 4 col groups of 32
    const int cta = blockIdx.x;

    // ---------------- phase 1: normalize (warp per row) ---------------------------
    #pragma unroll
    for (int it = 0; it < 4; it++) {
        const int grp = cta + it * NCTA;          // 16-row group
        if (grp < NROWS / 16) {
            const int row = grp * 16 + wid;
            const float* src = (row < NHALF) ? (z1 + (size_t)row * DDIM)
                                             : (z2 + (size_t)(row - NHALF) * DDIM);
            float4 v0 = ((const float4*)src)[lane];
            float4 v1 = ((const float4*)src)[lane + 32];
            float ss = v0.x * v0.x + v0.y * v0.y + v0.z * v0.z + v0.w * v0.w
                     + v1.x * v1.x + v1.y * v1.y + v1.z * v1.z + v1.w * v1.w;
            #pragma unroll
            for (int o = 16; o; o >>= 1) ss += __shfl_xor_sync(0xFFFFFFFFu, ss, o);
            const float rn = 1.0f / fmaxf(sqrtf(ss), 1e-8f);
            __nv_bfloat16* dst = g_zb + (size_t)row * DDIM;
            __nv_bfloat162 b0 = {__float2bfloat16(v0.x * rn), __float2bfloat16(v0.y * rn)};
            __nv_bfloat162 b1 = {__float2bfloat16(v0.z * rn), __float2bfloat16(v0.w * rn)};
            __nv_bfloat162 b2 = {__float2bfloat16(v1.x * rn), __float2bfloat16(v1.y * rn)};
            __nv_bfloat162 b3 = {__float2bfloat16(v1.z * rn), __float2bfloat16(v1.w * rn)};
            ((__nv_bfloat162*)dst)[lane * 2]            = b0;
            ((__nv_bfloat162*)dst)[lane * 2 + 1]        = b1;
            ((__nv_bfloat162*)dst)[(lane + 32) * 2]     = b2;
            ((__nv_bfloat162*)dst)[(lane + 32) * 2 + 1] = b3;
            if (lane == 0) g_rowsum[row] = 0.0f;
        }
    }

    // ---------------- grid barrier 1 ----------------------------------------------
    if (tid == 0) {
        __threadfence();
        atomicAdd(&g_cnt1, 1u);
        while (*(volatile unsigned*)&g_cnt1 < NCTA) { }
        __threadfence();
    }
    __syncthreads();

    // ---------------- phase 2: symmetric HMMA GEMM + exp + sums + pair -------------
    uint32_t d32 = smem_u32(dyn);
    char* base = dyn + ((1024u - (d32 & 1023u)) & 1023u);
    const uint32_t uA  = smem_u32(base);
    const uint32_t uB0 = uA + TILE_BYTES;
    const uint32_t uB1 = uA + 2 * TILE_BYTES;
    float* red_row = (float*)(base + 3 * TILE_BYTES);   // [4][128] by wn
    float* red_col = red_row + 4 * BM;                  // [4][128] by wm

    const int count = 14 + (cta < 8 ? 1 : 0);
    int rem = cta * 14 + (cta < 8 ? cta : 8);
    int p = 0;
    for (;;) {
        int L = NTILE - rowof(p);
        if (rem < L) break;
        rem -= L;
        p++;
    }
    int off = rem;

    int ti = rowof(p);
    tile_load(uA, ti * BM, tid);
    tile_load(uB0, (ti + off) * BM, tid);
    CP_COMMIT();
    int cur_ti = ti;

    for (int k = 0; k < count; k++) {
        ti = rowof(p);
        const int tj = ti + off;
        if (ti != cur_ti) {
            tile_load(uA, ti * BM, tid);
            CP_COMMIT();
            cur_ti = ti;
        }
        CP_WAIT0();
        __syncthreads();

        if (k + 1 < count) {
            int p2 = p, o2 = off + 1;
            if (o2 >= NTILE - rowof(p2)) { o2 = 0; p2++; }
            tile_load((k & 1) ? uB0 : uB1, (rowof(p2) + o2) * BM, tid);
            CP_COMMIT();
        }

        const uint32_t uBc = (k & 1) ? uB1 : uB0;
        const int i0 = ti * BM, j0 = tj * BM;
        const bool diag = (ti == tj);
        const bool pairt = (tj == ti + NHALF / BM);

        float acc[2][4][4];
        #pragma unroll
        for (int mf = 0; mf < 2; mf++)
            #pragma unroll
            for (int nf = 0; nf < 4; nf++)
                #pragma unroll
                for (int c = 0; c < 4; c++) acc[mf][nf][c] = 0.0f;

        #pragma unroll 4
        for (int ks = 0; ks < 16; ks++) {
            const int cch = ks * 2 + (lane >> 4);
            uint32_t af[2][4], bf[4][2];
            #pragma unroll
            for (int mf = 0; mf < 2; mf++) {
                int r = wm * 32 + mf * 16 + (lane & 15);
                ldsm_x4(tile_addr(uA, r, cch), af[mf]);
            }
            #pragma unroll
            for (int ng = 0; ng < 2; ng++) {
                int rn = wn * 32 + ng * 16 + (lane & 15);
                uint32_t q[4];
                ldsm_x4(tile_addr(uBc, rn, cch), q);
                bf[ng * 2 + 0][0] = q[0]; bf[ng * 2 + 0][1] = q[2];
                bf[ng * 2 + 1][0] = q[1]; bf[ng * 2 + 1][1] = q[3];
            }
            #pragma unroll
            for (int mf = 0; mf < 2; mf++)
                #pragma unroll
                for (int nf = 0; nf < 4; nf++)
                    mma16816(acc[mf][nf], af[mf], bf[nf]);
        }

        const int rloc = wm * 32 + (lane >> 2);
        const int cloc = wn * 32 + (lane & 3) * 2;
        float cs[8];
        #pragma unroll
        for (int x = 0; x < 8; x++) cs[x] = 0.0f;

        #pragma unroll
        for (int mf = 0; mf < 2; mf++) {
            const int rlo = i0 + rloc + mf * 16;
            const int rhi = rlo + 8;
            float slo = 0.0f, shi = 0.0f;
            #pragma unroll
            for (int nf = 0; nf < 4; nf++) {
                const int col = j0 + cloc + nf * 8;
                if (pairt) {
                    if ((rlo ^ NHALF) == col) {
                        float v = 2.0f * acc[mf][nf][0];
                        g_pair[rlo] = v; g_pair[col] = v;
                    }
                    if ((rlo ^ NHALF) == col + 1) {
                        float v = 2.0f * acc[mf][nf][1];
                        g_pair[rlo] = v; g_pair[col + 1] = v;
                    }
                    if ((rhi ^ NHALF) == col) {
                        float v = 2.0f * acc[mf][nf][2];
                        g_pair[rhi] = v; g_pair[col] = v;
                    }
                    if ((rhi ^ NHALF) == col + 1) {
                        float v = 2.0f * acc[mf][nf][3];
                        g_pair[rhi] = v; g_pair[col + 1] = v;
                    }
                }
                float e0 = __expf(2.0f * acc[mf][nf][0]);
                float e1 = __expf(2.0f * acc[mf][nf][1]);
                float e2 = __expf(2.0f * acc[mf][nf][2]);
                float e3 = __expf(2.0f * acc[mf][nf][3]);
                e0 = (rlo == col)     ? 0.0f : e0;
                e1 = (rlo == col + 1) ? 0.0f : e1;
                e2 = (rhi == col)     ? 0.0f : e2;
                e3 = (rhi == col + 1) ? 0.0f : e3;
                slo += e0 + e1;
                shi += e2 + e3;
                cs[nf * 2]     += e0 + e2;
                cs[nf * 2 + 1] += e1 + e3;
            }
            slo += __shfl_xor_sync(0xFFFFFFFFu, slo, 1);
            slo += __shfl_xor_sync(0xFFFFFFFFu, slo, 2);
            shi += __shfl_xor_sync(0xFFFFFFFFu, shi, 1);
            shi += __shfl_xor_sync(0xFFFFFFFFu, shi, 2);
            if ((lane & 3) == 0) {
                const int lrow = wm * 32 + mf * 16 + (lane >> 2);
                red_row[wn * BM + lrow] = slo;
                red_row[wn * BM + lrow + 8] = shi;
            }
        }
        if (!diag) {
            #pragma unroll
            for (int x = 0; x < 8; x++) {
                cs[x] += __shfl_xor_sync(0xFFFFFFFFu, cs[x], 4);
                cs[x] += __shfl_xor_sync(0xFFFFFFFFu, cs[x], 8);
                cs[x] += __shfl_xor_sync(0xFFFFFFFFu, cs[x], 16);
            }
            if (lane < 4) {
                #pragma unroll
                for (int nf = 0; nf < 4; nf++) {
                    const int c = wn * 32 + nf * 8 + lane * 2;
                    red_col[wm * BM + c]     = cs[nf * 2];
                    red_col[wm * BM + c + 1] = cs[nf * 2 + 1];
                }
            }
        }
        __syncthreads();
        if (tid < BM) {
            float s = red_row[tid] + red_row[BM + tid]
                    + red_row[2 * BM + tid] + red_row[3 * BM + tid];
            atomicAdd(&g_rowsum[i0 + tid], s);
        } else if (tid < 2 * BM && !diag) {
            const int c = tid - BM;
            float s = red_col[c] + red_col[BM + c]
                    + red_col[2 * BM + c] + red_col[3 * BM + c];
            atomicAdd(&g_rowsum[j0 + c], s);
        }

        off++;
        if (off >= NTILE - ti) { off = 0; p++; }
    }

    // ---------------- grid barrier 2 + CTA0 finish ---------------------------------
    if (tid == 0) {
        __threadfence();
        atomicAdd(&g_cnt2, 1u);
    }
    if (cta == 0) {
        if (tid == 0) {
            while (*(volatile unsigned*)&g_cnt2 < NCTA) { }
            __threadfence();
        }
        __syncthreads();
        __shared__ float sh[NTHREADS];
        float s = 0.0f;
        #pragma unroll
        for (int u = 0; u < NROWS / NTHREADS; u++) {
            const int r = tid + u * NTHREADS;
            s += logf(g_rowsum[r]) - g_pair[r];
        }
        sh[tid] = s;
        __syncthreads();
        for (int o2 = NTHREADS / 2; o2; o2 >>= 1) {
            if (tid < o2) sh[tid] += sh[tid + o2];
            __syncthreads();
        }
        if (tid == 0) {
            out[0] = sh[0] * (1.0f / (float)NROWS);
            g_cnt1 = 0;
            g_cnt2 = 0;
        }
    }
}

// ---------------------------------------------------------------- launch
extern "C" void kernel_launch(void* const* d_in, const int* in_sizes, int n_in,
                              void* d_out, int out_size) {
    const float* z1 = (const float*)d_in[0];
    const float* z2 = (const float*)d_in[1];
    float* out = (float*)d_out;

    static int smem_set = 0;
    if (!smem_set) {
        cudaFuncSetAttribute(k_fused, cudaFuncAttributeMaxDynamicSharedMemorySize,
                             3 * TILE_BYTES + RED_BYTES + 1024);
        smem_set = 1;
    }

    k_fused<<<NCTA, NTHREADS, 3 * TILE_BYTES + RED_BYTES + 1024>>>(z1, z2, out);
}